// round 9
// baseline (speedup 1.0000x reference)
#include <cuda_runtime.h>
#include <math.h>

// ---------------- static problem config ----------------
#define B_   8
#define Q_   20
#define P_   12
#define N_   4096
#define G_   2048
#define FAC_ 64
#define M_   1280
#define KNN_ 7
#define REP_EPS 1e-12f
#define BW2 0.0009f
#define RADIUS_ 0.07f

#define BM (B_*M_)           // 10240
#define BG (B_*G_)           // 16384

#define COST_BLOCKS (B_*P_)              // 96  (one block per cost ROW)
#define CH1_BLOCKS (B_*(M_/64))          // 160
#define CH2_BLOCKS (B_*(G_/64))          // 256
#define REP_BLOCKS (B_*Q_/4)             // 40
#define GEOM_TOTAL (CH1_BLOCKS + CH2_BLOCKS + REP_BLOCKS)       // 456
#define TOTAL_BLOCKS (1 + COST_BLOCKS + GEOM_TOTAL)             // 553

// ---------------- device scratch (zero is identity; solver restores zeros) ----------------
__device__ float g_cham [B_][Q_][P_];
__device__ float g_nsim [B_][Q_][P_];
__device__ float g_ddiff[B_][Q_][P_];
__device__ float g_costT[B_][P_][Q_];   // rows = gt planes, cols = queries
__device__ float g_cnt  [B_][P_];
__device__ int   g_rows [B_][P_];
__device__ float g_accs[8];             // 0=rep 1=mL1 2=mL2 3=gL1 4=gL2
__device__ int   g_rowmask[B_];         // bit p set when cost row p of batch b is ready
__device__ int   g_geom_done;

// ---------------- chamfer block helper: 64 src points, 4-way target slicing ----------------
__device__ __forceinline__ void chamfer_block(
    const float* __restrict__ srcBase, const float* __restrict__ tgtBase,
    int nTgt, int accL1, int accL2)
{
    int t = threadIdx.x;
    int pi = t & 63, s = t >> 6;
    float px = srcBase[pi*3+0], py = srcBase[pi*3+1], pz = srcBase[pi*3+2];
    float m1 = 1e30f, m2 = 1e30f;
    __shared__ float tx[256], ty[256], tz[256];
    for (int base = 0; base < nTgt; base += 256) {
        tx[t] = tgtBase[(base+t)*3+0];
        ty[t] = tgtBase[(base+t)*3+1];
        tz[t] = tgtBase[(base+t)*3+2];
        __syncthreads();
        int j0 = s * 64;
        #pragma unroll 8
        for (int j = j0; j < j0 + 64; j++) {
            float dx = px-tx[j], dy = py-ty[j], dz = pz-tz[j];
            float l1 = fabsf(dx) + fabsf(dy) + fabsf(dz);
            float l2 = fmaf(dx, dx, fmaf(dy, dy, dz*dz));
            m1 = fminf(m1, l1); m2 = fminf(m2, l2);
        }
        __syncthreads();
    }
    __shared__ float r1[256], r2[256];
    r1[t] = m1; r2[t] = m2;
    __syncthreads();
    if (t < 64) {
        float a1 = fminf(fminf(r1[t], r1[t+64]), fminf(r1[t+128], r1[t+192]));
        float a2 = fminf(fminf(r2[t], r2[t+64]), fminf(r2[t+128], r2[t+192]));
        #pragma unroll
        for (int off = 16; off; off >>= 1) {
            a1 += __shfl_down_sync(0xffffffffu, a1, off);
            a2 += __shfl_down_sync(0xffffffffu, a2, off);
        }
        if ((t & 31) == 0) { r1[t] = a1; r2[t] = a2; }
    }
    __syncthreads();
    if (t == 0) {
        atomicAdd(&g_accs[accL1], r1[0] + r1[32]);
        atomicAdd(&g_accs[accL2], r2[0] + r2[32]);
    }
}

// ---------------- the single fused kernel ----------------
__global__ void __launch_bounds__(256, 4) k_all(const float* __restrict__ points,
                       const float* __restrict__ pn, const float* __restrict__ pd,
                       const float* __restrict__ gn, const float* __restrict__ gd,
                       const void* __restrict__ mask,
                       const float* __restrict__ rec, const float* __restrict__ gt,
                       const float* __restrict__ logits, float* __restrict__ out)
{
    int bid = blockIdx.x;
    int t = threadIdx.x;

    if (bid == 0) {
        // ================= solver block: row-pipelined JV + cls + final =================
        __shared__ float cost_s[B_][P_*Q_];
        __shared__ float u_s[B_][P_ + 1];
        __shared__ float red[3][256];
        int w = t >> 5;        // warp = batch
        int lane = t & 31;
        const unsigned FULL = 0xffffffffu;

        if (lane <= P_) u_s[w][lane] = 0.f;

        float v = 0.f, minv = 0.f;
        int p = 0, way = 0, used = 0;
        unsigned free_mask = ((1u << Q_) - 1u) << 1;   // columns 1..Q_ free

        for (int i = 1; i <= P_; i++) {
            // wait until cost rows 0..i-1 of this batch are published
            int need = (1 << i) - 1;
            if (lane == 0) {
                while ((atomicOr(&g_rowmask[w], 0) & need) != need) __nanosleep(32);
            }
            __syncwarp();
            __threadfence();
            // load row i (first use) into shared
            if (lane >= 1 && lane <= Q_)
                cost_s[w][(i-1)*Q_ + (lane-1)] = g_costT[w][i-1][lane-1];
            __syncwarp();

            if (lane == 0) p = i;
            minv = 1e30f; used = 0;
            int j0 = 0;
            while (true) {
                if (lane == j0) used = 1;
                int i0 = __shfl_sync(FULL, p, j0);
                float u0 = u_s[w][i0];
                bool active = (lane >= 1) && (lane <= Q_) && !used;
                if (active) {
                    float cur = fmaxf(cost_s[w][(i0-1)*Q_ + (lane-1)] - u0 - v, 0.f);
                    if (cur < minv) { minv = cur; way = j0; }
                }
                unsigned key = active ? ((__float_as_uint(minv) & ~31u) | (unsigned)lane)
                                      : 0xFFFFFFFFu;
                key = __reduce_min_sync(FULL, key);
                int j1 = (int)(key & 31u);
                float delta = __shfl_sync(FULL, minv, j1);
                if (lane <= Q_) {
                    if (used)           { u_s[w][p] += delta; v -= delta; }
                    else if (lane >= 1) { minv -= delta; }
                }
                __syncwarp();
                j0 = j1;
                if ((free_mask >> j0) & 1u) break;    // landed on an unassigned column
            }
            free_mask &= ~(1u << j0);                 // it becomes assigned now
            // augment along alternating path
            while (j0 != 0) {
                int wy = __shfl_sync(FULL, way, j0);
                int pw = __shfl_sync(FULL, p, wy);
                if (lane == j0) p = pw;
                j0 = wy;
            }
        }
        if (lane >= 1 && lane <= Q_ && p >= 1)
            g_rows[w][p - 1] = lane - 1;
        __syncthreads();

        // ---- cls / param / pvd ----
        float c_cls = 0.f, c_par = 0.f, c_pvd = 0.f;
        if (t < B_*Q_) {
            int b = t / Q_, q = t % Q_;
            float tgt = 0.f;
            #pragma unroll
            for (int pp = 0; pp < P_; pp++) tgt += (g_rows[b][pp] == q) ? 1.f : 0.f;
            float x = logits[t];
            c_cls = fmaxf(x, 0.f) - x*tgt + log1pf(expf(-fabsf(x)));
        }
        if (t < B_*P_) {
            int b = t / P_, pp = t % P_;
            int r = g_rows[b][pp];
            c_par = g_nsim[b][r][pp] + g_ddiff[b][r][pp];
            c_pvd = (g_cnt[b][pp] > 0.f) ? g_cham[b][r][pp] : 0.f;
        }
        red[0][t] = c_cls; red[1][t] = c_par; red[2][t] = c_pvd;
        __syncthreads();
        for (int off = 128; off; off >>= 1) {
            if (t < off) {
                red[0][t] += red[0][t+off]; red[1][t] += red[1][t+off]; red[2][t] += red[2][t+off];
            }
            __syncthreads();
        }

        if (t == 0) {
            while (atomicAdd(&g_geom_done, 0) < GEOM_TOTAL) __nanosleep(64);
            __threadfence();
            float ch1 = 0.5f * (g_accs[1] / (float)BM + g_accs[3] / (float)BG);
            float ch2 = 0.5f * (g_accs[2] / (float)BM + g_accs[4] / (float)BG);
            out[0] = red[0][0] / (float)(B_*Q_)
                   + 0.5f  * red[1][0] / (float)(B_*P_)
                   + 20.f  * red[2][0] / (float)(B_*P_)
                   + g_accs[0] / (float)(B_*Q_)
                   + ch1 + ch2;
        }
        __syncthreads();
        // restore state for next graph replay
        if (t < 8) g_accs[t] = 0.f;
        if (t < B_) g_rowmask[t] = 0;
        if (t == 0) g_geom_done = 0;
    } else if (bid <= COST_BLOCKS) {
        // ================= cost ROW (b, p): all 20 queries vs mask row p =================
        int id = bid - 1;
        int b = id / P_, p = id % P_;

        // mask dtype detection: block-parallel scan of first 8KB
        const unsigned char* mraw = (const unsigned char*)mask;
        bool big = false, odd = false;
        #pragma unroll 4
        for (int i = t*32; i < t*32 + 32; i++) {
            unsigned char vch = mraw[i];
            big |= (vch > 1);
            odd |= (vch == 1) && ((i & 3) != 0);
        }
        int anyBig = __syncthreads_or(big ? 1 : 0);
        int anyOdd = __syncthreads_or(odd ? 1 : 0);
        int mode = anyBig ? 1 : (anyOdd ? 0 : 2);   // 1=float32, 0=uint8, 2=int32

        __shared__ float4 s_qp[Q_];                 // (nx, ny, nz, d) per query
        __shared__ float s_acc[Q_];
        __shared__ float s_cntTot;
        if (t < Q_) {
            s_qp[t] = make_float4(pn[(b*Q_+t)*3+0], pn[(b*Q_+t)*3+1],
                                  pn[(b*Q_+t)*3+2], pd[b*Q_+t]);
            s_acc[t] = 0.f;
        }
        if (t == 0) s_cntTot = 0.f;
        __syncthreads();

        float acc[Q_];
        #pragma unroll
        for (int q = 0; q < Q_; q++) acc[q] = 0.f;
        float cnt = 0.f;

        const float* pb = points + (size_t)b * N_ * 3;
        const long mrow = ((long)b * P_ + p) * N_;
        for (int n = t; n < N_; n += 256) {
            float px = pb[n*3+0], py = pb[n*3+1], pz = pb[n*3+2];
            float mf;
            if (mode == 1)      mf = (((const float*)mask)[mrow + n] != 0.f) ? 1.f : 0.f;
            else if (mode == 0) mf = (((const unsigned char*)mask)[mrow + n] != 0) ? 1.f : 0.f;
            else                mf = (((const int*)mask)[mrow + n] != 0) ? 1.f : 0.f;
            cnt += mf;
            #pragma unroll
            for (int q = 0; q < Q_; q++) {
                float4 qp = s_qp[q];
                float dot = fmaf(px, qp.x, fmaf(py, qp.y, pz * qp.z));
                acc[q] = fmaf(mf, fabsf(dot - qp.w), acc[q]);
            }
        }
        #pragma unroll
        for (int off = 16; off; off >>= 1) cnt += __shfl_down_sync(0xffffffffu, cnt, off);
        if ((t & 31) == 0) atomicAdd(&s_cntTot, cnt);
        #pragma unroll
        for (int q = 0; q < Q_; q++) {
            float v = acc[q];
            #pragma unroll
            for (int off = 16; off; off >>= 1) v += __shfl_down_sync(0xffffffffu, v, off);
            if ((t & 31) == 0) atomicAdd(&s_acc[q], v);
        }
        __syncthreads();

        if (t < Q_) {
            int q = t;
            float c = s_cntTot;
            float cham = s_acc[q] / fmaxf(c, 1.f);
            float4 qp = s_qp[q];
            float ns = 1.f - fabsf(qp.x*gn[(b*P_+p)*3+0] + qp.y*gn[(b*P_+p)*3+1]
                                 + qp.z*gn[(b*P_+p)*3+2]);
            float dd = fabsf(qp.w - gd[b*P_ + p]);
            int has = c > 0.f;
            g_cham [b][q][p] = cham;
            g_nsim [b][q][p] = ns;
            g_ddiff[b][q][p] = dd;
            g_costT[b][p][q] = ns + 0.5f*dd + 5.f*(has ? cham : 1.f);
            if (q == 0) g_cnt[b][p] = c;
        }
        __syncthreads();
        if (t == 0) {
            __threadfence();
            atomicOr(&g_rowmask[b], 1 << p);
        }
    } else if (bid <= COST_BLOCKS + CH1_BLOCKS) {
        int id = bid - 1 - COST_BLOCKS;
        int b  = id / (M_/64);
        int mc = id % (M_/64);
        chamfer_block(rec + ((size_t)b*M_ + mc*64)*3, gt + (size_t)b*G_*3, G_, 1, 2);
        if (t == 0) { __threadfence(); atomicAdd(&g_geom_done, 1); }
    } else if (bid <= COST_BLOCKS + CH1_BLOCKS + CH2_BLOCKS) {
        int id = bid - 1 - COST_BLOCKS - CH1_BLOCKS;
        int b  = id / (G_/64);
        int gc = id % (G_/64);
        chamfer_block(gt + ((size_t)b*G_ + gc*64)*3, rec + (size_t)b*M_*3, M_, 3, 4);
        if (t == 0) { __threadfence(); atomicAdd(&g_geom_done, 1); }
    } else {
        // ================= repulsion: 4 (b,q) groups per block =================
        int id = bid - 1 - COST_BLOCKS - CH1_BLOCKS - CH2_BLOCKS;   // 0..39
        int sub = t >> 6;
        int i = t & 63;
        int gq = id*4 + sub;
        int b = gq / Q_, q = gq % Q_;
        __shared__ float sx[4][FAC_], sy[4][FAC_], sz[4][FAC_];
        const float* base = rec + ((size_t)b*M_ + q*FAC_)*3;
        sx[sub][i] = base[i*3+0]; sy[sub][i] = base[i*3+1]; sz[sub][i] = base[i*3+2];
        __syncthreads();
        float px = sx[sub][i], py = sy[sub][i], pz = sz[sub][i];
        float best[KNN_];
        #pragma unroll
        for (int k = 0; k < KNN_; k++) best[k] = 1e30f;
        for (int j = 0; j < FAC_; j++) {
            if (j == i) continue;
            float dx = px-sx[sub][j], dy = py-sy[sub][j], dz = pz-sz[sub][j];
            float vv = fmaf(dx, dx, fmaf(dy, dy, dz*dz));
            #pragma unroll
            for (int k = 0; k < KNN_; k++) {
                float lo = fminf(best[k], vv);
                vv = fmaxf(best[k], vv);
                best[k] = lo;
            }
        }
        float s = 0.f;
        #pragma unroll
        for (int k = 0; k < KNN_; k++) {
            float dn = fmaxf(best[k], REP_EPS);
            s += (RADIUS_ - sqrtf(dn)) * expf(-dn / BW2);
        }
        #pragma unroll
        for (int off = 16; off; off >>= 1) s += __shfl_down_sync(0xffffffffu, s, off);
        __shared__ float sw[8];
        if ((t & 31) == 0) sw[t >> 5] = s;
        __syncthreads();
        if (i == 0) {
            float tot = sw[sub*2] + sw[sub*2 + 1];
            atomicAdd(&g_accs[0], fmaxf(tot / (float)(FAC_*KNN_), 0.f));
        }
        __syncthreads();
        if (t == 0) { __threadfence(); atomicAdd(&g_geom_done, 1); }
    }
}

// ---------------- host launcher ----------------
extern "C" void kernel_launch(void* const* d_in, const int* in_sizes, int n_in,
                              void* d_out, int out_size) {
    const float* pred_logits = nullptr;
    const float* pred_normals = nullptr;
    const float* pred_distances = nullptr;
    const float* gt_normals = nullptr;
    const float* gt_distances = nullptr;
    const void*  gt_masks = nullptr;
    const float* points = nullptr;
    const float* rec = nullptr;
    const float* gt = nullptr;
    int seen160 = 0;
    for (int i = 0; i < n_in; i++) {
        switch (in_sizes[i]) {
            case B_ * Q_:
                if (seen160++ == 0) pred_logits = (const float*)d_in[i];
                else pred_distances = (const float*)d_in[i];
                break;
            case B_ * Q_ * 3: pred_normals = (const float*)d_in[i]; break;
            case B_ * P_ * 3: gt_normals = (const float*)d_in[i]; break;
            case B_ * P_: gt_distances = (const float*)d_in[i]; break;
            case B_ * P_ * N_: gt_masks = d_in[i]; break;
            case B_ * N_ * 3: points = (const float*)d_in[i]; break;
            case B_ * M_ * 3: rec = (const float*)d_in[i]; break;
            case B_ * G_ * 3: gt = (const float*)d_in[i]; break;
            default: break;  // gt_index unused
        }
    }

    k_all<<<TOTAL_BLOCKS, 256>>>(points, pred_normals, pred_distances,
                                 gt_normals, gt_distances, gt_masks, rec, gt,
                                 pred_logits, (float*)d_out);
}

// round 11
// speedup vs baseline: 1.5474x; 1.5474x over previous
#include <cuda_runtime.h>
#include <math.h>

// ---------------- static problem config ----------------
#define B_   8
#define Q_   20
#define P_   12
#define N_   4096
#define G_   2048
#define FAC_ 64
#define M_   1280
#define KNN_ 7
#define REP_EPS 1e-12f
#define BW2 0.0009f
#define RADIUS_ 0.07f

#define BM (B_*M_)           // 10240
#define BG (B_*G_)           // 16384

#define COST_BLOCKS (B_*Q_)              // 160
#define CH1_BLOCKS (B_*(M_/64))          // 160
#define CH2_BLOCKS (B_*(G_/64))          // 256
#define REP_BLOCKS (B_*Q_/4)             // 40
#define K1_BLOCKS (COST_BLOCKS + CH1_BLOCKS + CH2_BLOCKS + REP_BLOCKS)  // 616

// ---------------- device scratch (zero is identity; k2 restores zeros) ----------------
__device__ float g_cham [B_][Q_][P_];
__device__ float g_nsim [B_][Q_][P_];
__device__ float g_ddiff[B_][Q_][P_];
__device__ float g_costT[B_][P_][Q_];   // rows = gt planes, cols = queries
__device__ float g_cnt  [B_][P_];
__device__ int   g_rows [B_][P_];
__device__ float g_accs[8];             // 0=rep 1=mL1 2=mL2 3=gL1 4=gL2

// order-preserving float->uint key (handles negatives)
__device__ __forceinline__ unsigned fkey(float f) {
    unsigned b = __float_as_uint(f);
    return b ^ ((b >> 31) ? 0xFFFFFFFFu : 0x80000000u);
}

// ---------------- masked accumulation helper ----------------
template<int MODE>
__device__ __forceinline__ void accum_masked(const void* __restrict__ mask, long mbase,
    const float* __restrict__ pb, float nx, float ny, float nz, float dq,
    int tid, float* acc, float* cnt)
{
    for (int n = tid; n < N_; n += 256) {
        float px = pb[n*3+0], py = pb[n*3+1], pz = pb[n*3+2];
        float pp = fabsf(px*nx + py*ny + pz*nz - dq);
        #pragma unroll
        for (int p = 0; p < P_; p++) {
            long idx = mbase + (long)p * N_ + n;
            bool m;
            if (MODE == 0)      m = ((const unsigned char*)mask)[idx] != 0;
            else if (MODE == 1) m = ((const float*)mask)[idx] != 0.f;
            else                m = ((const int*)mask)[idx] != 0;
            acc[p] += m ? pp : 0.f;
            cnt[p] += m ? 1.f : 0.f;
        }
    }
}

// ---------------- chamfer block helper: 64 src points, float4 targets ----------------
__device__ __forceinline__ void chamfer_block(
    const float* __restrict__ srcBase, const float* __restrict__ tgtBase,
    int nTgt, int accL1, int accL2)
{
    int t = threadIdx.x;
    int pi = t & 63, s = t >> 6;
    float px = srcBase[pi*3+0], py = srcBase[pi*3+1], pz = srcBase[pi*3+2];
    float m1 = 1e30f, m2 = 1e30f;
    __shared__ float4 t4[256];
    for (int base = 0; base < nTgt; base += 256) {
        t4[t] = make_float4(tgtBase[(base+t)*3+0], tgtBase[(base+t)*3+1],
                            tgtBase[(base+t)*3+2], 0.f);
        __syncthreads();
        int j0 = s * 64;
        #pragma unroll 8
        for (int j = j0; j < j0 + 64; j++) {
            float4 w = t4[j];
            float dx = px-w.x, dy = py-w.y, dz = pz-w.z;
            float l1 = fabsf(dx) + fabsf(dy) + fabsf(dz);
            float l2 = fmaf(dx, dx, fmaf(dy, dy, dz*dz));
            m1 = fminf(m1, l1); m2 = fminf(m2, l2);
        }
        __syncthreads();
    }
    __shared__ float r1[256], r2[256];
    r1[t] = m1; r2[t] = m2;
    __syncthreads();
    if (t < 64) {
        float a1 = fminf(fminf(r1[t], r1[t+64]), fminf(r1[t+128], r1[t+192]));
        float a2 = fminf(fminf(r2[t], r2[t+64]), fminf(r2[t+128], r2[t+192]));
        #pragma unroll
        for (int off = 16; off; off >>= 1) {
            a1 += __shfl_down_sync(0xffffffffu, a1, off);
            a2 += __shfl_down_sync(0xffffffffu, a2, off);
        }
        if ((t & 31) == 0) { r1[t] = a1; r2[t] = a2; }
    }
    __syncthreads();
    if (t == 0) {
        atomicAdd(&g_accs[accL1], r1[0] + r1[32]);
        atomicAdd(&g_accs[accL2], r2[0] + r2[32]);
    }
}

// ---------------- kernel 1: cost matrix + chamfer + repulsion (fused grid) ----------------
__global__ void __launch_bounds__(256) k1(const float* __restrict__ points,
                       const float* __restrict__ pn, const float* __restrict__ pd,
                       const float* __restrict__ gn, const float* __restrict__ gd,
                       const void* __restrict__ mask,
                       const float* __restrict__ rec, const float* __restrict__ gt)
{
    int bid = blockIdx.x;
    int t = threadIdx.x;

    if (bid < COST_BLOCKS) {
        int b = bid / Q_, q = bid % Q_;

        // mask dtype detection: block-parallel scan of first 8KB
        const unsigned char* mraw = (const unsigned char*)mask;
        bool big = false, odd = false;
        #pragma unroll 4
        for (int i = t*32; i < t*32 + 32; i++) {
            unsigned char vch = mraw[i];
            big |= (vch > 1);
            odd |= (vch == 1) && ((i & 3) != 0);
        }
        int anyBig = __syncthreads_or(big ? 1 : 0);
        int anyOdd = __syncthreads_or(odd ? 1 : 0);
        int mode = anyBig ? 1 : (anyOdd ? 0 : 2);

        float nx = pn[(b*Q_ + q)*3 + 0];
        float ny = pn[(b*Q_ + q)*3 + 1];
        float nz = pn[(b*Q_ + q)*3 + 2];
        float dq = pd[b*Q_ + q];

        __shared__ float s_acc[P_], s_cnt[P_];
        if (t < P_) { s_acc[t] = 0.f; s_cnt[t] = 0.f; }
        __syncthreads();

        float acc[P_], cnt[P_];
        #pragma unroll
        for (int p = 0; p < P_; p++) { acc[p] = 0.f; cnt[p] = 0.f; }

        const float* pb = points + (size_t)b * N_ * 3;
        const long mbase = (long)b * P_ * N_;
        if (mode == 1)      accum_masked<1>(mask, mbase, pb, nx, ny, nz, dq, t, acc, cnt);
        else if (mode == 0) accum_masked<0>(mask, mbase, pb, nx, ny, nz, dq, t, acc, cnt);
        else                accum_masked<2>(mask, mbase, pb, nx, ny, nz, dq, t, acc, cnt);

        #pragma unroll
        for (int p = 0; p < P_; p++) {
            float v = acc[p], c = cnt[p];
            #pragma unroll
            for (int off = 16; off; off >>= 1) {
                v += __shfl_down_sync(0xffffffffu, v, off);
                c += __shfl_down_sync(0xffffffffu, c, off);
            }
            if ((t & 31) == 0) { atomicAdd(&s_acc[p], v); atomicAdd(&s_cnt[p], c); }
        }
        __syncthreads();

        if (t < P_) {
            int p = t;
            float c = s_cnt[p];
            float cham = s_acc[p] / fmaxf(c, 1.f);
            float ns = 1.f - fabsf(nx*gn[(b*P_+p)*3+0] + ny*gn[(b*P_+p)*3+1] + nz*gn[(b*P_+p)*3+2]);
            float dd = fabsf(dq - gd[b*P_ + p]);
            int has = c > 0.f;
            g_cham [b][q][p] = cham;
            g_nsim [b][q][p] = ns;
            g_ddiff[b][q][p] = dd;
            g_costT[b][p][q] = ns + 0.5f*dd + 5.f*(has ? cham : 1.f);
            if (q == 0) g_cnt[b][p] = c;
        }
    } else if (bid < COST_BLOCKS + CH1_BLOCKS) {
        int id = bid - COST_BLOCKS;
        int b  = id / (M_/64);
        int mc = id % (M_/64);
        chamfer_block(rec + ((size_t)b*M_ + mc*64)*3, gt + (size_t)b*G_*3, G_, 1, 2);
    } else if (bid < COST_BLOCKS + CH1_BLOCKS + CH2_BLOCKS) {
        int id = bid - COST_BLOCKS - CH1_BLOCKS;
        int b  = id / (G_/64);
        int gc = id % (G_/64);
        chamfer_block(gt + ((size_t)b*G_ + gc*64)*3, rec + (size_t)b*M_*3, M_, 3, 4);
    } else {
        // repulsion: 4 (b,q) groups per block
        int id = bid - COST_BLOCKS - CH1_BLOCKS - CH2_BLOCKS;   // 0..39
        int sub = t >> 6;
        int i = t & 63;
        int gq = id*4 + sub;
        int b = gq / Q_, q = gq % Q_;
        __shared__ float sx[4][FAC_], sy[4][FAC_], sz[4][FAC_];
        const float* base = rec + ((size_t)b*M_ + q*FAC_)*3;
        sx[sub][i] = base[i*3+0]; sy[sub][i] = base[i*3+1]; sz[sub][i] = base[i*3+2];
        __syncthreads();
        float px = sx[sub][i], py = sy[sub][i], pz = sz[sub][i];
        float best[KNN_];
        #pragma unroll
        for (int k = 0; k < KNN_; k++) best[k] = 1e30f;
        for (int j = 0; j < FAC_; j++) {
            if (j == i) continue;
            float dx = px-sx[sub][j], dy = py-sy[sub][j], dz = pz-sz[sub][j];
            float vv = fmaf(dx, dx, fmaf(dy, dy, dz*dz));
            #pragma unroll
            for (int k = 0; k < KNN_; k++) {
                float lo = fminf(best[k], vv);
                vv = fmaxf(best[k], vv);
                best[k] = lo;
            }
        }
        float s = 0.f;
        #pragma unroll
        for (int k = 0; k < KNN_; k++) {
            float dn = fmaxf(best[k], REP_EPS);
            s += (RADIUS_ - sqrtf(dn)) * expf(-dn / BW2);
        }
        #pragma unroll
        for (int off = 16; off; off >>= 1) s += __shfl_down_sync(0xffffffffu, s, off);
        __shared__ float sw[8];
        if ((t & 31) == 0) sw[t >> 5] = s;
        __syncthreads();
        if (i == 0) {
            float tot = sw[sub*2] + sw[sub*2 + 1];
            atomicAdd(&g_accs[0], fmaxf(tot / (float)(FAC_*KNN_), 0.f));
        }
    }
}

// ---------------- kernel 2: greedy-init JV Hungarian + cls + final combine ----------------
__global__ void __launch_bounds__(256) k2(const float* __restrict__ logits,
                                          float* __restrict__ out)
{
    __shared__ float cost_s[B_][P_*Q_];
    __shared__ float u_s[B_][P_ + 1];
    __shared__ float red[3][256];
    int t = threadIdx.x;
    int w = t >> 5;        // warp = batch
    int lane = t & 31;
    const unsigned FULL = 0xffffffffu;

    const float* csrc = &g_costT[0][0][0];
    for (int idx = t; idx < B_*P_*Q_; idx += 256)
        (&cost_s[0][0])[idx] = csrc[idx];
    __syncthreads();
    if (lane == 0) u_s[w][0] = 0.f;

    // ---- greedy row-reduction init ----
    float v = 0.f;
    int p = 0;                                       // lane j: row assigned to col j (0 = free)
    unsigned free_mask = ((1u << Q_) - 1u) << 1;     // cols 1..Q_ free
    unsigned todo = 0;                               // rows needing augmentation (bitmask)
    for (int i = 1; i <= P_; i++) {
        float c = (lane >= 1 && lane <= Q_) ? cost_s[w][(i-1)*Q_ + (lane-1)] : 1e30f;
        unsigned key = (lane >= 1 && lane <= Q_) ? ((fkey(c) & ~31u) | (unsigned)lane)
                                                 : 0xFFFFFFFFu;
        key = __reduce_min_sync(FULL, key);
        int jm = (int)(key & 31u);
        float ui = __shfl_sync(FULL, c, jm);         // row minimum
        if (lane == 0) u_s[w][i] = ui;
        if ((free_mask >> jm) & 1u) {                // argmin column free -> assign
            if (lane == jm) p = i;
            free_mask &= ~(1u << jm);
        } else {
            todo |= (1u << i);
        }
    }
    __syncwarp();

    // ---- augment remaining rows (e-maxx JV with warp-parallel Dijkstra) ----
    float minv = 0.f;
    int way = 0, used = 0;
    for (int i = 1; i <= P_; i++) {
        if (!((todo >> i) & 1u)) continue;
        if (lane == 0) p = i;
        minv = 1e30f; used = 0;
        int j0 = 0;
        while (true) {
            if (lane == j0) used = 1;
            int i0 = __shfl_sync(FULL, p, j0);
            float u0 = u_s[w][i0];
            bool active = (lane >= 1) && (lane <= Q_) && !used;
            if (active) {
                float cur = cost_s[w][(i0-1)*Q_ + (lane-1)] - u0 - v;
                if (cur < minv) { minv = cur; way = j0; }
            }
            unsigned key = active ? ((fkey(minv) & ~31u) | (unsigned)lane)
                                  : 0xFFFFFFFFu;
            key = __reduce_min_sync(FULL, key);
            int j1 = (int)(key & 31u);
            float delta = __shfl_sync(FULL, minv, j1);
            if (lane <= Q_) {
                if (used)           { u_s[w][p] += delta; v -= delta; }
                else if (lane >= 1) { minv -= delta; }
            }
            __syncwarp();
            j0 = j1;
            if ((free_mask >> j0) & 1u) break;
        }
        free_mask &= ~(1u << j0);
        while (j0 != 0) {
            int wy = __shfl_sync(FULL, way, j0);
            int pw = __shfl_sync(FULL, p, wy);
            if (lane == j0) p = pw;
            j0 = wy;
        }
    }
    if (lane >= 1 && lane <= Q_ && p >= 1)
        g_rows[w][p - 1] = lane - 1;
    __syncthreads();

    // ---- cls / param / pvd ----
    float c_cls = 0.f, c_par = 0.f, c_pvd = 0.f;
    if (t < B_*Q_) {
        int b = t / Q_, q = t % Q_;
        float tgt = 0.f;
        #pragma unroll
        for (int pp = 0; pp < P_; pp++) tgt += (g_rows[b][pp] == q) ? 1.f : 0.f;
        float x = logits[t];
        c_cls = fmaxf(x, 0.f) - x*tgt + log1pf(expf(-fabsf(x)));
    }
    if (t < B_*P_) {
        int b = t / P_, pp = t % P_;
        int r = g_rows[b][pp];
        c_par = g_nsim[b][r][pp] + g_ddiff[b][r][pp];
        c_pvd = (g_cnt[b][pp] > 0.f) ? g_cham[b][r][pp] : 0.f;
    }
    red[0][t] = c_cls; red[1][t] = c_par; red[2][t] = c_pvd;
    __syncthreads();
    for (int off = 128; off; off >>= 1) {
        if (t < off) {
            red[0][t] += red[0][t+off]; red[1][t] += red[1][t+off]; red[2][t] += red[2][t+off];
        }
        __syncthreads();
    }
    if (t == 0) {
        float ch1 = 0.5f * (g_accs[1] / (float)BM + g_accs[3] / (float)BG);
        float ch2 = 0.5f * (g_accs[2] / (float)BM + g_accs[4] / (float)BG);
        out[0] = red[0][0] / (float)(B_*Q_)
               + 0.5f  * red[1][0] / (float)(B_*P_)
               + 20.f  * red[2][0] / (float)(B_*P_)
               + g_accs[0] / (float)(B_*Q_)
               + ch1 + ch2;
    }
    if (t < 8) g_accs[t] = 0.f;   // restore for next graph replay
}

// ---------------- host launcher ----------------
extern "C" void kernel_launch(void* const* d_in, const int* in_sizes, int n_in,
                              void* d_out, int out_size) {
    const float* pred_logits = nullptr;
    const float* pred_normals = nullptr;
    const float* pred_distances = nullptr;
    const float* gt_normals = nullptr;
    const float* gt_distances = nullptr;
    const void*  gt_masks = nullptr;
    const float* points = nullptr;
    const float* rec = nullptr;
    const float* gt = nullptr;
    int seen160 = 0;
    for (int i = 0; i < n_in; i++) {
        switch (in_sizes[i]) {
            case B_ * Q_:
                if (seen160++ == 0) pred_logits = (const float*)d_in[i];
                else pred_distances = (const float*)d_in[i];
                break;
            case B_ * Q_ * 3: pred_normals = (const float*)d_in[i]; break;
            case B_ * P_ * 3: gt_normals = (const float*)d_in[i]; break;
            case B_ * P_: gt_distances = (const float*)d_in[i]; break;
            case B_ * P_ * N_: gt_masks = d_in[i]; break;
            case B_ * N_ * 3: points = (const float*)d_in[i]; break;
            case B_ * M_ * 3: rec = (const float*)d_in[i]; break;
            case B_ * G_ * 3: gt = (const float*)d_in[i]; break;
            default: break;  // gt_index unused
        }
    }

    k1<<<K1_BLOCKS, 256>>>(points, pred_normals, pred_distances,
                           gt_normals, gt_distances, gt_masks, rec, gt);
    k2<<<1, 256>>>(pred_logits, (float*)d_out);
}